// round 2
// baseline (speedup 1.0000x reference)
#include <cuda_runtime.h>

#define N_NODES 50000
#define N_EDGES 640000
#define FDIM    128
#define OUT_DIM 16
#define BATCH   2
#define M_ROWS  (BATCH * N_NODES)   /* 100000 flattened rows */
#define EPSBN   1e-5f

// ---------------- scratch (device globals; no allocation allowed) -------------
__device__ __align__(128) float g_xw  [(size_t)M_ROWS * FDIM];  // GEMM outputs
__device__ __align__(128) float g_t   [(size_t)M_ROWS * FDIM];  // relu(conv) activations
__device__ __align__(128) float g_dinv[N_NODES];
__device__ __align__(128) float g_deg [N_NODES];
__device__ __align__(128) int   g_cnt   [N_NODES];
__device__ __align__(128) int   g_start [N_NODES + 1];
__device__ __align__(128) int   g_cursor[N_NODES];
__device__ __align__(128) uint2 g_edge  [N_EDGES];              // {src, norm-bits} sorted by dst
__device__ __align__(128) float g_W2p [FDIM * FDIM];
__device__ __align__(128) float g_cvec[FDIM];
__device__ __align__(128) float g_Wcp [FDIM * OUT_DIM];
__device__ __align__(128) float g_bcp [OUT_DIM];
__device__ __align__(128) float g_sum [FDIM];
__device__ __align__(128) float g_sq  [FDIM];

// ---------------- init: deg=1 (self loop), cnt=0 ----------------------------
__global__ void k_init(float* deg, int* cnt) {
    int i = blockIdx.x * blockDim.x + threadIdx.x;
    if (i < N_NODES) { deg[i] = 1.0f; cnt[i] = 0; }
}

// ---------------- pass1: degree accumulation + dst histogram -----------------
__global__ void k_pass1(const float* __restrict__ ewp, const int* __restrict__ col,
                        float* deg, int* cnt) {
    int e = blockIdx.x * blockDim.x + threadIdx.x;
    if (e < N_EDGES) {
        int c = col[e];
        atomicAdd(&deg[c], expf(ewp[e]));
        atomicAdd(&cnt[c], 1);
    }
}

__global__ void k_dinv(const float* __restrict__ deg, float* dinv) {
    int i = blockIdx.x * blockDim.x + threadIdx.x;
    if (i < N_NODES) {
        float d = deg[i];
        dinv[i] = (d > 0.f) ? rsqrtf(d) : 0.f;
    }
}

// ---------------- single-block exclusive scan of counts ----------------------
__global__ void k_scan(const int* __restrict__ cnt, int* __restrict__ start,
                       int* __restrict__ cursor) {
    __shared__ int sh[1024];
    const int tid = threadIdx.x;
    const int CH = 49;                         // 1024*49 = 50176 >= N_NODES
    const int base = tid * CH;
    int local = 0;
    for (int i = 0; i < CH; i++) {
        int idx = base + i;
        if (idx < N_NODES) local += cnt[idx];
    }
    sh[tid] = local;
    __syncthreads();
    for (int off = 1; off < 1024; off <<= 1) {
        int v = 0;
        if (tid >= off) v = sh[tid - off];
        __syncthreads();
        sh[tid] += v;
        __syncthreads();
    }
    int run = sh[tid] - local;                 // exclusive prefix
    for (int i = 0; i < CH; i++) {
        int idx = base + i;
        if (idx < N_NODES) {
            start[idx] = run;
            cursor[idx] = run;
            run += cnt[idx];
        }
    }
    if (tid == 1023) start[N_NODES] = N_EDGES;
}

// ---------------- bucket scatter: sorted {src, norm} per destination ---------
__global__ void k_sortedges(const float* __restrict__ ewp, const int* __restrict__ row,
                            const int* __restrict__ col, const float* __restrict__ dinv,
                            int* cursor, uint2* __restrict__ edge) {
    int e = blockIdx.x * blockDim.x + threadIdx.x;
    if (e < N_EDGES) {
        int r = row[e];
        int c = col[e];
        float nm = dinv[r] * expf(ewp[e]) * dinv[c];
        int pos = atomicAdd(&cursor[c], 1);
        edge[pos] = make_uint2((unsigned)r, __float_as_uint(nm));
    }
}

// ---------------- GEMM: C[M x128] = A[M x128] @ W[128x128] (+ cvec) ----------
__global__ __launch_bounds__(256) void k_gemm128(const float* __restrict__ A,
                                                 const float* __restrict__ W,
                                                 const float* __restrict__ cvec,
                                                 float* __restrict__ C, int Mrows) {
    extern __shared__ float smem[];
    float* sW = smem;            // 128*128 floats = 64 KB
    float* sA = smem + 16384;    // 64*128 floats = 32 KB
    const int tid = threadIdx.x;

    {   // load W once per block
        const float4* W4 = (const float4*)W;
        float4* sW4 = (float4*)sW;
        #pragma unroll
        for (int i = 0; i < 16; i++) sW4[tid + i * 256] = W4[tid + i * 256];
    }

    const int tc = tid & 15;   // cols 8*tc .. 8*tc+7
    const int tr = tid >> 4;   // rows 4*tr .. 4*tr+3

    unsigned long long initc[4];
    if (cvec) {
        #pragma unroll
        for (int p = 0; p < 4; p++) {
            float2 cv2 = *(const float2*)(cvec + 8 * tc + 2 * p);
            asm("mov.b64 %0, {%1, %2};" : "=l"(initc[p]) : "f"(cv2.x), "f"(cv2.y));
        }
    } else {
        #pragma unroll
        for (int p = 0; p < 4; p++) initc[p] = 0ull;
    }

    const int ntiles = (Mrows + 63) >> 6;
    for (int tile = blockIdx.x; tile < ntiles; tile += gridDim.x) {
        const int base = tile << 6;
        __syncthreads();
        #pragma unroll
        for (int i = 0; i < 8; i++) {
            int f4 = tid + i * 256;
            int r = f4 >> 5;
            int c4 = f4 & 31;
            int grow = base + r;
            float4 v = make_float4(0.f, 0.f, 0.f, 0.f);
            if (grow < Mrows) v = ((const float4*)A)[(size_t)grow * 32 + c4];
            ((float4*)sA)[f4] = v;
        }
        __syncthreads();

        unsigned long long acc[4][4];
        #pragma unroll
        for (int r = 0; r < 4; r++)
            #pragma unroll
            for (int p = 0; p < 4; p++) acc[r][p] = initc[p];

        const float* aBase = sA + (tr << 2) * FDIM;
        #pragma unroll 2
        for (int k0 = 0; k0 < FDIM; k0 += 4) {
            float4 a0 = *(const float4*)(aBase + k0);
            float4 a1 = *(const float4*)(aBase + FDIM + k0);
            float4 a2 = *(const float4*)(aBase + 2 * FDIM + k0);
            float4 a3 = *(const float4*)(aBase + 3 * FDIM + k0);
            float am[4][4] = {{a0.x, a0.y, a0.z, a0.w}, {a1.x, a1.y, a1.z, a1.w},
                              {a2.x, a2.y, a2.z, a2.w}, {a3.x, a3.y, a3.z, a3.w}};
            #pragma unroll
            for (int kk = 0; kk < 4; kk++) {
                const ulonglong2* bp = (const ulonglong2*)(sW + (k0 + kk) * FDIM + (tc << 3));
                ulonglong2 b01 = bp[0];
                ulonglong2 b23 = bp[1];
                unsigned long long bv[4] = {b01.x, b01.y, b23.x, b23.y};
                unsigned long long pa[4];
                #pragma unroll
                for (int r = 0; r < 4; r++)
                    asm("mov.b64 %0, {%1, %1};" : "=l"(pa[r]) : "f"(am[r][kk]));
                #pragma unroll
                for (int r = 0; r < 4; r++)
                    #pragma unroll
                    for (int p = 0; p < 4; p++)
                        asm("fma.rn.f32x2 %0, %1, %2, %0;"
                            : "+l"(acc[r][p]) : "l"(pa[r]), "l"(bv[p]));
            }
        }

        #pragma unroll
        for (int r = 0; r < 4; r++) {
            int grow = base + (tr << 2) + r;
            if (grow < Mrows) {
                ulonglong2* cp = (ulonglong2*)(C + (size_t)grow * FDIM + (tc << 3));
                cp[0] = make_ulonglong2(acc[r][0], acc[r][1]);
                cp[1] = make_ulonglong2(acc[r][2], acc[r][3]);
            }
        }
    }
}

// ---------------- fused aggregate + self-loop + bias + relu + BN stats -------
// warp per (node, batch) pair; adjacent warps share the node's edge list (L1 hit)
__global__ __launch_bounds__(256) void k_agg(const float* __restrict__ xw,
                                             const uint2* __restrict__ edge,
                                             const int* __restrict__ start,
                                             const float* __restrict__ dinv,
                                             const float* __restrict__ bias,
                                             float* __restrict__ t,
                                             float* __restrict__ gsum,
                                             float* __restrict__ gsq) {
    const int tid = threadIdx.x;
    const int lane = tid & 31;
    const int gw = (blockIdx.x * blockDim.x + tid) >> 5;
    const int nwarps = (gridDim.x * blockDim.x) >> 5;
    const float4 bv = ((const float4*)bias)[lane];
    float s[4] = {0.f, 0.f, 0.f, 0.f}, q[4] = {0.f, 0.f, 0.f, 0.f};

    for (int p = gw; p < 2 * N_NODES; p += nwarps) {
        const int n = p >> 1;
        const int b = p & 1;
        const float* xwb = xw + (size_t)b * N_NODES * FDIM;
        const int st = start[n];
        const int en = start[n + 1];
        const float d = dinv[n];
        const float d2 = d * d;
        float4 v = __ldg((const float4*)(xwb + (size_t)n * FDIM) + lane);
        float4 acc = make_float4(d2 * v.x, d2 * v.y, d2 * v.z, d2 * v.w);

        int e = st;
        for (; e + 4 <= en; e += 4) {
            uint2 m0 = __ldg(&edge[e]);
            uint2 m1 = __ldg(&edge[e + 1]);
            uint2 m2 = __ldg(&edge[e + 2]);
            uint2 m3 = __ldg(&edge[e + 3]);
            float4 a0 = __ldg((const float4*)(xwb + (size_t)m0.x * FDIM) + lane);
            float4 a1 = __ldg((const float4*)(xwb + (size_t)m1.x * FDIM) + lane);
            float4 a2 = __ldg((const float4*)(xwb + (size_t)m2.x * FDIM) + lane);
            float4 a3 = __ldg((const float4*)(xwb + (size_t)m3.x * FDIM) + lane);
            float w0 = __uint_as_float(m0.y), w1 = __uint_as_float(m1.y);
            float w2 = __uint_as_float(m2.y), w3 = __uint_as_float(m3.y);
            acc.x = fmaf(w0, a0.x, acc.x); acc.y = fmaf(w0, a0.y, acc.y);
            acc.z = fmaf(w0, a0.z, acc.z); acc.w = fmaf(w0, a0.w, acc.w);
            acc.x = fmaf(w1, a1.x, acc.x); acc.y = fmaf(w1, a1.y, acc.y);
            acc.z = fmaf(w1, a1.z, acc.z); acc.w = fmaf(w1, a1.w, acc.w);
            acc.x = fmaf(w2, a2.x, acc.x); acc.y = fmaf(w2, a2.y, acc.y);
            acc.z = fmaf(w2, a2.z, acc.z); acc.w = fmaf(w2, a2.w, acc.w);
            acc.x = fmaf(w3, a3.x, acc.x); acc.y = fmaf(w3, a3.y, acc.y);
            acc.z = fmaf(w3, a3.z, acc.z); acc.w = fmaf(w3, a3.w, acc.w);
        }
        for (; e < en; e++) {
            uint2 m = __ldg(&edge[e]);
            float4 a = __ldg((const float4*)(xwb + (size_t)m.x * FDIM) + lane);
            float w = __uint_as_float(m.y);
            acc.x = fmaf(w, a.x, acc.x); acc.y = fmaf(w, a.y, acc.y);
            acc.z = fmaf(w, a.z, acc.z); acc.w = fmaf(w, a.w, acc.w);
        }

        float4 o;
        o.x = fmaxf(acc.x + bv.x, 0.f);
        o.y = fmaxf(acc.y + bv.y, 0.f);
        o.z = fmaxf(acc.z + bv.z, 0.f);
        o.w = fmaxf(acc.w + bv.w, 0.f);
        ((float4*)(t + (size_t)(b * N_NODES + n) * FDIM))[lane] = o;
        s[0] += o.x; q[0] += o.x * o.x;
        s[1] += o.y; q[1] += o.y * o.y;
        s[2] += o.z; q[2] += o.z * o.z;
        s[3] += o.w; q[3] += o.w * o.w;
    }

    __shared__ float sh[256 * 8];
    #pragma unroll
    for (int j = 0; j < 4; j++) { sh[tid * 8 + j] = s[j]; sh[tid * 8 + 4 + j] = q[j]; }
    __syncthreads();
    if (tid < 32) {
        float as[4] = {0.f, 0.f, 0.f, 0.f}, aq[4] = {0.f, 0.f, 0.f, 0.f};
        for (int w = 0; w < 8; w++) {
            int src = (tid + 32 * w) * 8;
            #pragma unroll
            for (int j = 0; j < 4; j++) { as[j] += sh[src + j]; aq[j] += sh[src + 4 + j]; }
        }
        #pragma unroll
        for (int j = 0; j < 4; j++) {
            atomicAdd(&gsum[4 * tid + j], as[j]);
            atomicAdd(&gsq [4 * tid + j], aq[j]);
        }
    }
}

// ---------------- fold BN into next weight matrix ----------------------------
__global__ void k_fold(const float* __restrict__ gsum, const float* __restrict__ gsq,
                       const float* __restrict__ gamma, const float* __restrict__ beta,
                       const float* __restrict__ Wsrc, int J,
                       const float* __restrict__ extra_bias,
                       float* __restrict__ Wp, float* __restrict__ cv) {
    __shared__ float ssc[FDIM], ssh[FDIM];
    int t = threadIdx.x;  // 128
    float mu = gsum[t] * (1.0f / M_ROWS);
    float var = gsq[t] * (1.0f / M_ROWS) - mu * mu;
    float sc = gamma[t] * rsqrtf(var + EPSBN);
    ssc[t] = sc;
    ssh[t] = beta[t] - mu * sc;
    __syncthreads();
    if (t < J) {
        float acc = extra_bias ? extra_bias[t] : 0.f;
        for (int k = 0; k < FDIM; k++) {
            float w = Wsrc[k * J + t];
            Wp[k * J + t] = ssc[k] * w;
            acc += ssh[k] * w;
        }
        cv[t] = acc;
    }
}

// ---------------- classifier: out = t2 @ Wcp + bcp ---------------------------
__global__ void k_classifier(const float* __restrict__ t2, const float* __restrict__ Wcp,
                             const float* __restrict__ bcp, float* __restrict__ out) {
    __shared__ float sWT[OUT_DIM * FDIM];  // [o][k]
    __shared__ float sb[OUT_DIM];
    int tid = threadIdx.x;  // 256
    for (int i = tid; i < FDIM * OUT_DIM; i += 256) {
        int k = i / OUT_DIM, o = i % OUT_DIM;
        sWT[o * FDIM + k] = Wcp[i];
    }
    if (tid < OUT_DIM) sb[tid] = bcp[tid];
    __syncthreads();

    int gt = blockIdx.x * blockDim.x + tid;
    int warp = gt >> 5;
    int lane = gt & 31;
    int nw = (gridDim.x * blockDim.x) >> 5;
    for (int rowM = warp; rowM < M_ROWS; rowM += nw) {
        float4 v = __ldg((const float4*)(t2 + (size_t)rowM * FDIM) + lane);
        float y[OUT_DIM];
        #pragma unroll
        for (int o = 0; o < OUT_DIM; o++) {
            float4 w = ((const float4*)(sWT + o * FDIM))[lane];
            y[o] = v.x * w.x + v.y * w.y + v.z * w.z + v.w * w.w;
        }
        #pragma unroll
        for (int off = 16; off; off >>= 1)
            #pragma unroll
            for (int o = 0; o < OUT_DIM; o++)
                y[o] += __shfl_xor_sync(0xffffffffu, y[o], off);
        if (lane < OUT_DIM) out[(size_t)rowM * OUT_DIM + lane] = y[lane] + sb[lane];
    }
}

// ---------------- launch -----------------------------------------------------
extern "C" void kernel_launch(void* const* d_in, const int* in_sizes, int n_in,
                              void* d_out, int out_size) {
    const float* x   = (const float*)d_in[0];
    const int*   ei  = (const int*)d_in[1];
    const float* ewp = (const float*)d_in[2];
    const float* W1  = (const float*)d_in[3];
    const float* b1  = (const float*)d_in[4];
    const float* W2  = (const float*)d_in[5];
    const float* b2  = (const float*)d_in[6];
    const float* g1  = (const float*)d_in[7];
    const float* be1 = (const float*)d_in[8];
    const float* g2  = (const float*)d_in[9];
    const float* be2 = (const float*)d_in[10];
    const float* Wc  = (const float*)d_in[11];
    const float* bc  = (const float*)d_in[12];
    float* out = (float*)d_out;
    const int* row = ei;
    const int* col = ei + N_EDGES;

    float *p_xw, *p_t, *p_dinv, *p_deg;
    float *p_W2p, *p_cvec, *p_Wcp, *p_bcp, *p_sum, *p_sq;
    int *p_cnt, *p_start, *p_cursor;
    uint2* p_edge;
    cudaGetSymbolAddress((void**)&p_xw,   g_xw);
    cudaGetSymbolAddress((void**)&p_t,    g_t);
    cudaGetSymbolAddress((void**)&p_dinv, g_dinv);
    cudaGetSymbolAddress((void**)&p_deg,  g_deg);
    cudaGetSymbolAddress((void**)&p_cnt,  g_cnt);
    cudaGetSymbolAddress((void**)&p_start, g_start);
    cudaGetSymbolAddress((void**)&p_cursor, g_cursor);
    cudaGetSymbolAddress((void**)&p_edge, g_edge);
    cudaGetSymbolAddress((void**)&p_W2p,  g_W2p);
    cudaGetSymbolAddress((void**)&p_cvec, g_cvec);
    cudaGetSymbolAddress((void**)&p_Wcp,  g_Wcp);
    cudaGetSymbolAddress((void**)&p_bcp,  g_bcp);
    cudaGetSymbolAddress((void**)&p_sum,  g_sum);
    cudaGetSymbolAddress((void**)&p_sq,   g_sq);

    (void)cudaFuncSetAttribute(k_gemm128, cudaFuncAttributeMaxDynamicSharedMemorySize, 98304);

    // --- CSR build + normalization (overlaps nothing; all tiny) ---
    k_init      <<<(N_NODES + 255) / 256, 256>>>(p_deg, p_cnt);
    k_pass1     <<<(N_EDGES + 255) / 256, 256>>>(ewp, col, p_deg, p_cnt);
    k_dinv      <<<(N_NODES + 255) / 256, 256>>>(p_deg, p_dinv);
    k_scan      <<<1, 1024>>>(p_cnt, p_start, p_cursor);
    k_sortedges <<<(N_EDGES + 255) / 256, 256>>>(ewp, row, col, p_dinv, p_cursor, p_edge);

    // --- layer 1 ---
    k_gemm128<<<592, 256, 98304>>>(x, W1, nullptr, p_xw, M_ROWS);
    cudaMemsetAsync(p_sum, 0, FDIM * sizeof(float), 0);
    cudaMemsetAsync(p_sq,  0, FDIM * sizeof(float), 0);
    k_agg<<<1184, 256>>>(p_xw, p_edge, p_start, p_dinv, b1, p_t, p_sum, p_sq);
    k_fold<<<1, 128>>>(p_sum, p_sq, g1, be1, W2, FDIM, nullptr, p_W2p, p_cvec);

    // --- layer 2 (BN1 folded into W2) ---
    k_gemm128<<<592, 256, 98304>>>(p_t, p_W2p, p_cvec, p_xw, M_ROWS);
    cudaMemsetAsync(p_sum, 0, FDIM * sizeof(float), 0);
    cudaMemsetAsync(p_sq,  0, FDIM * sizeof(float), 0);
    k_agg<<<1184, 256>>>(p_xw, p_edge, p_start, p_dinv, b2, p_t, p_sum, p_sq);
    k_fold<<<1, 128>>>(p_sum, p_sq, g2, be2, Wc, OUT_DIM, bc, p_Wcp, p_bcp);

    // --- classifier (BN2 folded into Wc) ---
    k_classifier<<<1024, 256>>>(p_t, p_Wcp, p_bcp, out);
}

// round 3
// speedup vs baseline: 1.5188x; 1.5188x over previous
#include <cuda_runtime.h>

#define N_NODES 50000
#define N_EDGES 640000
#define FDIM    128
#define OUT_DIM 16
#define BATCH   2
#define M_ROWS  (BATCH * N_NODES)   /* 100000 flattened rows */
#define EPSBN   1e-5f
#define NBLK_SCAN ((N_NODES + 255) / 256)   /* 196 */

// ---------------- scratch (device globals; no allocation allowed) -------------
__device__ __align__(128) float g_xw  [(size_t)M_ROWS * FDIM];  // GEMM outputs
__device__ __align__(128) float g_t   [(size_t)M_ROWS * FDIM];  // relu(conv) activations
__device__ __align__(128) float g_dinv[N_NODES];
__device__ __align__(128) float g_deg [N_NODES];
__device__ __align__(128) int   g_cnt   [N_NODES];
__device__ __align__(128) int   g_start [N_NODES + 1];
__device__ __align__(128) int   g_cursor[N_NODES];
__device__ __align__(128) int   g_partial[256];
__device__ __align__(128) int   g_pscan  [256];
__device__ __align__(128) uint2 g_edge  [N_EDGES];              // {src, norm-bits} sorted by dst
__device__ __align__(128) float g_W2p [FDIM * FDIM];
__device__ __align__(128) float g_cvec[FDIM];
__device__ __align__(128) float g_Wcp [FDIM * OUT_DIM];
__device__ __align__(128) float g_bcp [OUT_DIM];
__device__ __align__(128) float g_sum [FDIM];
__device__ __align__(128) float g_sq  [FDIM];

// ---------------- init: deg=1 (self loop), cnt=0 ----------------------------
__global__ void k_init(float* deg, int* cnt) {
    int i = blockIdx.x * blockDim.x + threadIdx.x;
    if (i < N_NODES) { deg[i] = 1.0f; cnt[i] = 0; }
}

// ---------------- pass1: degree accumulation + dst histogram -----------------
__global__ void k_pass1(const float* __restrict__ ewp, const int* __restrict__ col,
                        float* deg, int* cnt) {
    int e = blockIdx.x * blockDim.x + threadIdx.x;
    if (e < N_EDGES) {
        int c = col[e];
        atomicAdd(&deg[c], expf(ewp[e]));
        atomicAdd(&cnt[c], 1);
    }
}

__global__ void k_dinv(const float* __restrict__ deg, float* dinv) {
    int i = blockIdx.x * blockDim.x + threadIdx.x;
    if (i < N_NODES) {
        float d = deg[i];
        dinv[i] = (d > 0.f) ? rsqrtf(d) : 0.f;
    }
}

// ---------------- hierarchical scan (3 kernels, all coalesced) ---------------
__global__ void k_scan1(const int* __restrict__ cnt, int* __restrict__ partial) {
    __shared__ int sh[8];
    int idx = blockIdx.x * 256 + threadIdx.x;
    int v = (idx < N_NODES) ? cnt[idx] : 0;
    #pragma unroll
    for (int off = 16; off; off >>= 1) v += __shfl_down_sync(0xffffffffu, v, off);
    if ((threadIdx.x & 31) == 0) sh[threadIdx.x >> 5] = v;
    __syncthreads();
    if (threadIdx.x == 0) {
        int s = 0;
        #pragma unroll
        for (int w = 0; w < 8; w++) s += sh[w];
        partial[blockIdx.x] = s;
    }
}

__global__ void k_scan2(const int* __restrict__ partial, int* __restrict__ pscan,
                        int* __restrict__ start) {
    __shared__ int sh[256];
    int t = threadIdx.x;
    int v = (t < NBLK_SCAN) ? partial[t] : 0;
    sh[t] = v;
    __syncthreads();
    #pragma unroll
    for (int off = 1; off < 256; off <<= 1) {
        int u = (t >= off) ? sh[t - off] : 0;
        __syncthreads();
        sh[t] += u;
        __syncthreads();
    }
    if (t < NBLK_SCAN) pscan[t] = sh[t] - v;   // exclusive
    if (t == 0) start[N_NODES] = N_EDGES;
}

__global__ void k_scan3(const int* __restrict__ cnt, const int* __restrict__ pscan,
                        int* __restrict__ start, int* __restrict__ cursor) {
    __shared__ int sh[256];
    int t = threadIdx.x;
    int idx = blockIdx.x * 256 + t;
    int v = (idx < N_NODES) ? cnt[idx] : 0;
    sh[t] = v;
    __syncthreads();
    #pragma unroll
    for (int off = 1; off < 256; off <<= 1) {
        int u = (t >= off) ? sh[t - off] : 0;
        __syncthreads();
        sh[t] += u;
        __syncthreads();
    }
    if (idx < N_NODES) {
        int excl = sh[t] - v + pscan[blockIdx.x];
        start[idx] = excl;
        cursor[idx] = excl;
    }
}

// ---------------- bucket scatter: sorted {src, norm} per destination ---------
__global__ void k_sortedges(const float* __restrict__ ewp, const int* __restrict__ row,
                            const int* __restrict__ col, const float* __restrict__ dinv,
                            int* cursor, uint2* __restrict__ edge) {
    int e = blockIdx.x * blockDim.x + threadIdx.x;
    if (e < N_EDGES) {
        int r = row[e];
        int c = col[e];
        float nm = dinv[r] * expf(ewp[e]) * dinv[c];
        int pos = atomicAdd(&cursor[c], 1);
        edge[pos] = make_uint2((unsigned)r, __float_as_uint(nm));
    }
}

// ---------------- GEMM: C[M x128] = A[M x128] @ W[128x128] (+ cvec) ----------
__global__ __launch_bounds__(256) void k_gemm128(const float* __restrict__ A,
                                                 const float* __restrict__ W,
                                                 const float* __restrict__ cvec,
                                                 float* __restrict__ C, int Mrows) {
    extern __shared__ float smem[];
    float* sW = smem;            // 128*128 floats = 64 KB
    float* sA = smem + 16384;    // 64*128 floats = 32 KB
    const int tid = threadIdx.x;

    {   // load W once per block
        const float4* W4 = (const float4*)W;
        float4* sW4 = (float4*)sW;
        #pragma unroll
        for (int i = 0; i < 16; i++) sW4[tid + i * 256] = W4[tid + i * 256];
    }

    const int tc = tid & 15;   // cols 8*tc .. 8*tc+7
    const int tr = tid >> 4;   // rows 4*tr .. 4*tr+3

    unsigned long long initc[4];
    if (cvec) {
        #pragma unroll
        for (int p = 0; p < 4; p++) {
            float2 cv2 = *(const float2*)(cvec + 8 * tc + 2 * p);
            asm("mov.b64 %0, {%1, %2};" : "=l"(initc[p]) : "f"(cv2.x), "f"(cv2.y));
        }
    } else {
        #pragma unroll
        for (int p = 0; p < 4; p++) initc[p] = 0ull;
    }

    const int ntiles = (Mrows + 63) >> 6;
    for (int tile = blockIdx.x; tile < ntiles; tile += gridDim.x) {
        const int base = tile << 6;
        __syncthreads();
        #pragma unroll
        for (int i = 0; i < 8; i++) {
            int f4 = tid + i * 256;
            int r = f4 >> 5;
            int c4 = f4 & 31;
            int grow = base + r;
            float4 v = make_float4(0.f, 0.f, 0.f, 0.f);
            if (grow < Mrows) v = ((const float4*)A)[(size_t)grow * 32 + c4];
            ((float4*)sA)[f4] = v;
        }
        __syncthreads();

        unsigned long long acc[4][4];
        #pragma unroll
        for (int r = 0; r < 4; r++)
            #pragma unroll
            for (int p = 0; p < 4; p++) acc[r][p] = initc[p];

        const float* aBase = sA + (tr << 2) * FDIM;
        #pragma unroll 2
        for (int k0 = 0; k0 < FDIM; k0 += 4) {
            float4 a0 = *(const float4*)(aBase + k0);
            float4 a1 = *(const float4*)(aBase + FDIM + k0);
            float4 a2 = *(const float4*)(aBase + 2 * FDIM + k0);
            float4 a3 = *(const float4*)(aBase + 3 * FDIM + k0);
            float am[4][4] = {{a0.x, a0.y, a0.z, a0.w}, {a1.x, a1.y, a1.z, a1.w},
                              {a2.x, a2.y, a2.z, a2.w}, {a3.x, a3.y, a3.z, a3.w}};
            #pragma unroll
            for (int kk = 0; kk < 4; kk++) {
                const ulonglong2* bp = (const ulonglong2*)(sW + (k0 + kk) * FDIM + (tc << 3));
                ulonglong2 b01 = bp[0];
                ulonglong2 b23 = bp[1];
                unsigned long long bv[4] = {b01.x, b01.y, b23.x, b23.y};
                unsigned long long pa[4];
                #pragma unroll
                for (int r = 0; r < 4; r++)
                    asm("mov.b64 %0, {%1, %1};" : "=l"(pa[r]) : "f"(am[r][kk]));
                #pragma unroll
                for (int r = 0; r < 4; r++)
                    #pragma unroll
                    for (int p = 0; p < 4; p++)
                        asm("fma.rn.f32x2 %0, %1, %2, %0;"
                            : "+l"(acc[r][p]) : "l"(pa[r]), "l"(bv[p]));
            }
        }

        #pragma unroll
        for (int r = 0; r < 4; r++) {
            int grow = base + (tr << 2) + r;
            if (grow < Mrows) {
                ulonglong2* cp = (ulonglong2*)(C + (size_t)grow * FDIM + (tc << 3));
                cp[0] = make_ulonglong2(acc[r][0], acc[r][1]);
                cp[1] = make_ulonglong2(acc[r][2], acc[r][3]);
            }
        }
    }
}

// ---------------- fused aggregate + self-loop + bias + relu + BN stats -------
// ONE batch per launch (keeps 51MB xw slice L2-resident); warp per node;
// edge-meta software pipelining to break the meta->gather dependency chain.
__global__ __launch_bounds__(256) void k_agg(const float* __restrict__ xwb,
                                             const uint2* __restrict__ edge,
                                             const int* __restrict__ start,
                                             const float* __restrict__ dinv,
                                             const float* __restrict__ bias,
                                             float* __restrict__ tb,
                                             float* __restrict__ gsum,
                                             float* __restrict__ gsq) {
    const int tid = threadIdx.x;
    const int lane = tid & 31;
    const int gw = (blockIdx.x * blockDim.x + tid) >> 5;
    const int nwarps = (gridDim.x * blockDim.x) >> 5;
    const float4 bv = ((const float4*)bias)[lane];
    float s[4] = {0.f, 0.f, 0.f, 0.f}, q[4] = {0.f, 0.f, 0.f, 0.f};

    for (int n = gw; n < N_NODES; n += nwarps) {
        const int st = start[n];
        const int en = start[n + 1];
        const float d = dinv[n];
        const float d2 = d * d;
        float4 v = __ldg((const float4*)(xwb + (size_t)n * FDIM) + lane);
        float4 acc = make_float4(d2 * v.x, d2 * v.y, d2 * v.z, d2 * v.w);

        const int cnt4 = (en - st) >> 2;
        int e = st;
        if (cnt4 > 0) {
            uint2 m0 = __ldg(&edge[e]);
            uint2 m1 = __ldg(&edge[e + 1]);
            uint2 m2 = __ldg(&edge[e + 2]);
            uint2 m3 = __ldg(&edge[e + 3]);
            for (int g = 0; g < cnt4; g++) {
                uint2 p0, p1, p2, p3;
                const int ne = e + 4;
                if (g + 1 < cnt4) {             // prefetch next group's metadata
                    p0 = __ldg(&edge[ne]);
                    p1 = __ldg(&edge[ne + 1]);
                    p2 = __ldg(&edge[ne + 2]);
                    p3 = __ldg(&edge[ne + 3]);
                }
                float4 a0 = __ldg((const float4*)(xwb + (size_t)m0.x * FDIM) + lane);
                float4 a1 = __ldg((const float4*)(xwb + (size_t)m1.x * FDIM) + lane);
                float4 a2 = __ldg((const float4*)(xwb + (size_t)m2.x * FDIM) + lane);
                float4 a3 = __ldg((const float4*)(xwb + (size_t)m3.x * FDIM) + lane);
                float w0 = __uint_as_float(m0.y), w1 = __uint_as_float(m1.y);
                float w2 = __uint_as_float(m2.y), w3 = __uint_as_float(m3.y);
                acc.x = fmaf(w0, a0.x, acc.x); acc.y = fmaf(w0, a0.y, acc.y);
                acc.z = fmaf(w0, a0.z, acc.z); acc.w = fmaf(w0, a0.w, acc.w);
                acc.x = fmaf(w1, a1.x, acc.x); acc.y = fmaf(w1, a1.y, acc.y);
                acc.z = fmaf(w1, a1.z, acc.z); acc.w = fmaf(w1, a1.w, acc.w);
                acc.x = fmaf(w2, a2.x, acc.x); acc.y = fmaf(w2, a2.y, acc.y);
                acc.z = fmaf(w2, a2.z, acc.z); acc.w = fmaf(w2, a2.w, acc.w);
                acc.x = fmaf(w3, a3.x, acc.x); acc.y = fmaf(w3, a3.y, acc.y);
                acc.z = fmaf(w3, a3.z, acc.z); acc.w = fmaf(w3, a3.w, acc.w);
                m0 = p0; m1 = p1; m2 = p2; m3 = p3;
                e = ne;
            }
        }
        for (; e < en; e++) {
            uint2 m = __ldg(&edge[e]);
            float4 a = __ldg((const float4*)(xwb + (size_t)m.x * FDIM) + lane);
            float w = __uint_as_float(m.y);
            acc.x = fmaf(w, a.x, acc.x); acc.y = fmaf(w, a.y, acc.y);
            acc.z = fmaf(w, a.z, acc.z); acc.w = fmaf(w, a.w, acc.w);
        }

        float4 o;
        o.x = fmaxf(acc.x + bv.x, 0.f);
        o.y = fmaxf(acc.y + bv.y, 0.f);
        o.z = fmaxf(acc.z + bv.z, 0.f);
        o.w = fmaxf(acc.w + bv.w, 0.f);
        ((float4*)(tb + (size_t)n * FDIM))[lane] = o;
        s[0] += o.x; q[0] += o.x * o.x;
        s[1] += o.y; q[1] += o.y * o.y;
        s[2] += o.z; q[2] += o.z * o.z;
        s[3] += o.w; q[3] += o.w * o.w;
    }

    __shared__ float sh[256 * 8];
    #pragma unroll
    for (int j = 0; j < 4; j++) { sh[tid * 8 + j] = s[j]; sh[tid * 8 + 4 + j] = q[j]; }
    __syncthreads();
    if (tid < 32) {
        float as[4] = {0.f, 0.f, 0.f, 0.f}, aq[4] = {0.f, 0.f, 0.f, 0.f};
        for (int w = 0; w < 8; w++) {
            int src = (tid + 32 * w) * 8;
            #pragma unroll
            for (int j = 0; j < 4; j++) { as[j] += sh[src + j]; aq[j] += sh[src + 4 + j]; }
        }
        #pragma unroll
        for (int j = 0; j < 4; j++) {
            atomicAdd(&gsum[4 * tid + j], as[j]);
            atomicAdd(&gsq [4 * tid + j], aq[j]);
        }
    }
}

// ---------------- fold BN into next weight matrix ----------------------------
__global__ void k_fold(const float* __restrict__ gsum, const float* __restrict__ gsq,
                       const float* __restrict__ gamma, const float* __restrict__ beta,
                       const float* __restrict__ Wsrc, int J,
                       const float* __restrict__ extra_bias,
                       float* __restrict__ Wp, float* __restrict__ cv) {
    __shared__ float ssc[FDIM], ssh[FDIM];
    int t = threadIdx.x;  // 128
    float mu = gsum[t] * (1.0f / M_ROWS);
    float var = gsq[t] * (1.0f / M_ROWS) - mu * mu;
    float sc = gamma[t] * rsqrtf(var + EPSBN);
    ssc[t] = sc;
    ssh[t] = beta[t] - mu * sc;
    __syncthreads();
    if (t < J) {
        float acc = extra_bias ? extra_bias[t] : 0.f;
        for (int k = 0; k < FDIM; k++) {
            float w = Wsrc[k * J + t];
            Wp[k * J + t] = ssc[k] * w;
            acc += ssh[k] * w;
        }
        cv[t] = acc;
    }
}

// ---------------- classifier: out = t2 @ Wcp + bcp ---------------------------
__global__ void k_classifier(const float* __restrict__ t2, const float* __restrict__ Wcp,
                             const float* __restrict__ bcp, float* __restrict__ out) {
    __shared__ float sWT[OUT_DIM * FDIM];  // [o][k]
    __shared__ float sb[OUT_DIM];
    int tid = threadIdx.x;  // 256
    for (int i = tid; i < FDIM * OUT_DIM; i += 256) {
        int k = i / OUT_DIM, o = i % OUT_DIM;
        sWT[o * FDIM + k] = Wcp[i];
    }
    if (tid < OUT_DIM) sb[tid] = bcp[tid];
    __syncthreads();

    int gt = blockIdx.x * blockDim.x + tid;
    int warp = gt >> 5;
    int lane = gt & 31;
    int nw = (gridDim.x * blockDim.x) >> 5;
    for (int rowM = warp; rowM < M_ROWS; rowM += nw) {
        float4 v = __ldg((const float4*)(t2 + (size_t)rowM * FDIM) + lane);
        float y[OUT_DIM];
        #pragma unroll
        for (int o = 0; o < OUT_DIM; o++) {
            float4 w = ((const float4*)(sWT + o * FDIM))[lane];
            y[o] = v.x * w.x + v.y * w.y + v.z * w.z + v.w * w.w;
        }
        #pragma unroll
        for (int off = 16; off; off >>= 1)
            #pragma unroll
            for (int o = 0; o < OUT_DIM; o++)
                y[o] += __shfl_xor_sync(0xffffffffu, y[o], off);
        if (lane < OUT_DIM) out[(size_t)rowM * OUT_DIM + lane] = y[lane] + sb[lane];
    }
}

// ---------------- launch -----------------------------------------------------
extern "C" void kernel_launch(void* const* d_in, const int* in_sizes, int n_in,
                              void* d_out, int out_size) {
    const float* x   = (const float*)d_in[0];
    const int*   ei  = (const int*)d_in[1];
    const float* ewp = (const float*)d_in[2];
    const float* W1  = (const float*)d_in[3];
    const float* b1  = (const float*)d_in[4];
    const float* W2  = (const float*)d_in[5];
    const float* b2  = (const float*)d_in[6];
    const float* g1  = (const float*)d_in[7];
    const float* be1 = (const float*)d_in[8];
    const float* g2  = (const float*)d_in[9];
    const float* be2 = (const float*)d_in[10];
    const float* Wc  = (const float*)d_in[11];
    const float* bc  = (const float*)d_in[12];
    float* out = (float*)d_out;
    const int* row = ei;
    const int* col = ei + N_EDGES;

    float *p_xw, *p_t, *p_dinv, *p_deg;
    float *p_W2p, *p_cvec, *p_Wcp, *p_bcp, *p_sum, *p_sq;
    int *p_cnt, *p_start, *p_cursor, *p_partial, *p_pscan;
    uint2* p_edge;
    cudaGetSymbolAddress((void**)&p_xw,   g_xw);
    cudaGetSymbolAddress((void**)&p_t,    g_t);
    cudaGetSymbolAddress((void**)&p_dinv, g_dinv);
    cudaGetSymbolAddress((void**)&p_deg,  g_deg);
    cudaGetSymbolAddress((void**)&p_cnt,  g_cnt);
    cudaGetSymbolAddress((void**)&p_start, g_start);
    cudaGetSymbolAddress((void**)&p_cursor, g_cursor);
    cudaGetSymbolAddress((void**)&p_partial, g_partial);
    cudaGetSymbolAddress((void**)&p_pscan, g_pscan);
    cudaGetSymbolAddress((void**)&p_edge, g_edge);
    cudaGetSymbolAddress((void**)&p_W2p,  g_W2p);
    cudaGetSymbolAddress((void**)&p_cvec, g_cvec);
    cudaGetSymbolAddress((void**)&p_Wcp,  g_Wcp);
    cudaGetSymbolAddress((void**)&p_bcp,  g_bcp);
    cudaGetSymbolAddress((void**)&p_sum,  g_sum);
    cudaGetSymbolAddress((void**)&p_sq,   g_sq);

    (void)cudaFuncSetAttribute(k_gemm128, cudaFuncAttributeMaxDynamicSharedMemorySize, 98304);

    const size_t batchOff = (size_t)N_NODES * FDIM;

    // --- CSR build + normalization ---
    k_init      <<<(N_NODES + 255) / 256, 256>>>(p_deg, p_cnt);
    k_pass1     <<<(N_EDGES + 255) / 256, 256>>>(ewp, col, p_deg, p_cnt);
    k_dinv      <<<(N_NODES + 255) / 256, 256>>>(p_deg, p_dinv);
    k_scan1     <<<NBLK_SCAN, 256>>>(p_cnt, p_partial);
    k_scan2     <<<1, 256>>>(p_partial, p_pscan, p_start);
    k_scan3     <<<NBLK_SCAN, 256>>>(p_cnt, p_pscan, p_start, p_cursor);
    k_sortedges <<<(N_EDGES + 255) / 256, 256>>>(ewp, row, col, p_dinv, p_cursor, p_edge);

    // --- layer 1 ---
    k_gemm128<<<592, 256, 98304>>>(x, W1, nullptr, p_xw, M_ROWS);
    cudaMemsetAsync(p_sum, 0, FDIM * sizeof(float), 0);
    cudaMemsetAsync(p_sq,  0, FDIM * sizeof(float), 0);
    k_agg<<<1184, 256>>>(p_xw,            p_edge, p_start, p_dinv, b1, p_t,            p_sum, p_sq);
    k_agg<<<1184, 256>>>(p_xw + batchOff, p_edge, p_start, p_dinv, b1, p_t + batchOff, p_sum, p_sq);
    k_fold<<<1, 128>>>(p_sum, p_sq, g1, be1, W2, FDIM, nullptr, p_W2p, p_cvec);

    // --- layer 2 (BN1 folded into W2) ---
    k_gemm128<<<592, 256, 98304>>>(p_t, p_W2p, p_cvec, p_xw, M_ROWS);
    cudaMemsetAsync(p_sum, 0, FDIM * sizeof(float), 0);
    cudaMemsetAsync(p_sq,  0, FDIM * sizeof(float), 0);
    k_agg<<<1184, 256>>>(p_xw,            p_edge, p_start, p_dinv, b2, p_t,            p_sum, p_sq);
    k_agg<<<1184, 256>>>(p_xw + batchOff, p_edge, p_start, p_dinv, b2, p_t + batchOff, p_sum, p_sq);
    k_fold<<<1, 128>>>(p_sum, p_sq, g2, be2, Wc, OUT_DIM, bc, p_Wcp, p_bcp);

    // --- classifier (BN2 folded into Wc) ---
    k_classifier<<<1024, 256>>>(p_t, p_Wcp, p_bcp, out);
}